// round 1
// baseline (speedup 1.0000x reference)
#include <cuda_runtime.h>
#include <math.h>

#define SEQ 4096
#define DIM 1024

// Scratch (allocation-free: static device globals)
__device__ float g_Q[(size_t)SEQ * DIM];
__device__ float g_K[(size_t)SEQ * DIM];
__device__ float g_V[(size_t)SEQ * DIM];
__device__ float g_S[(size_t)SEQ * SEQ];

// ---------------------------------------------------------------------------
// SGEMM: C[M,N] = alpha * A[M,K] @ op(B)
//   TRANS_B = 0 : B is [K,N] row-major (NN)
//   TRANS_B = 1 : B is [N,K] row-major, use B^T (NT: C_ij = dot(A_i, B_j))
// Block tile 128x128, K-step 8, 256 threads, 8x8 per-thread microtile.
// M, N multiples of 128; K multiple of 8 (true for all shapes here).
// ---------------------------------------------------------------------------
template <int TRANS_B>
__global__ __launch_bounds__(256, 2)
void sgemm128(const float* __restrict__ A, const float* __restrict__ B,
              float* __restrict__ C, int M, int N, int K, float alpha)
{
    __shared__ float As[8][128];
    __shared__ float Bs[8][128];

    const int tid = threadIdx.x;
    const int bm = blockIdx.y * 128;
    const int bn = blockIdx.x * 128;
    const int tx = tid & 15;        // 0..15 -> N microtile
    const int ty = tid >> 4;        // 0..15 -> M microtile

    // A loader: 128 rows x 8 cols, 2 float4 per row
    const int a_row = tid >> 1;           // 0..127
    const int a_k   = (tid & 1) * 4;      // 0 or 4
    // B loader (NN): 8 rows x 128 cols, 32 float4 per row
    const int bn_row = tid >> 5;          // 0..7   (k)
    const int bn_col = (tid & 31) * 4;    // 0..124 (n)
    // B loader (NT): same shape as A loader
    const int bt_row = tid >> 1;          // 0..127 (n)
    const int bt_k   = (tid & 1) * 4;     // 0 or 4 (k)

    float acc[8][8];
#pragma unroll
    for (int i = 0; i < 8; i++)
#pragma unroll
        for (int j = 0; j < 8; j++) acc[i][j] = 0.0f;

    for (int kt = 0; kt < K; kt += 8) {
        // ---- load A tile (transposed into As[k][m]) ----
        {
            const float4 av = *reinterpret_cast<const float4*>(
                &A[(size_t)(bm + a_row) * K + kt + a_k]);
            As[a_k + 0][a_row] = av.x;
            As[a_k + 1][a_row] = av.y;
            As[a_k + 2][a_row] = av.z;
            As[a_k + 3][a_row] = av.w;
        }
        // ---- load B tile into Bs[k][n] ----
        if (TRANS_B == 0) {
            const float4 bv = *reinterpret_cast<const float4*>(
                &B[(size_t)(kt + bn_row) * N + bn + bn_col]);
            *reinterpret_cast<float4*>(&Bs[bn_row][bn_col]) = bv;
        } else {
            const float4 bv = *reinterpret_cast<const float4*>(
                &B[(size_t)(bn + bt_row) * K + kt + bt_k]);
            Bs[bt_k + 0][bt_row] = bv.x;
            Bs[bt_k + 1][bt_row] = bv.y;
            Bs[bt_k + 2][bt_row] = bv.z;
            Bs[bt_k + 3][bt_row] = bv.w;
        }
        __syncthreads();

#pragma unroll
        for (int k = 0; k < 8; k++) {
            float ar[8], br[8];
#pragma unroll
            for (int i = 0; i < 8; i++) ar[i] = As[k][ty * 8 + i];
#pragma unroll
            for (int j = 0; j < 8; j++) br[j] = Bs[k][tx * 8 + j];
#pragma unroll
            for (int i = 0; i < 8; i++)
#pragma unroll
                for (int j = 0; j < 8; j++)
                    acc[i][j] = fmaf(ar[i], br[j], acc[i][j]);
        }
        __syncthreads();
    }

    // ---- epilogue ----
#pragma unroll
    for (int i = 0; i < 8; i++) {
        const size_t crow = (size_t)(bm + ty * 8 + i) * N + bn + tx * 8;
        float4 o0, o1;
        o0.x = alpha * acc[i][0]; o0.y = alpha * acc[i][1];
        o0.z = alpha * acc[i][2]; o0.w = alpha * acc[i][3];
        o1.x = alpha * acc[i][4]; o1.y = alpha * acc[i][5];
        o1.z = alpha * acc[i][6]; o1.w = alpha * acc[i][7];
        *reinterpret_cast<float4*>(&C[crow])     = o0;
        *reinterpret_cast<float4*>(&C[crow + 4]) = o1;
    }
}

// ---------------------------------------------------------------------------
// Row softmax, in place. One block (256 threads) per row of length n.
// ---------------------------------------------------------------------------
__global__ __launch_bounds__(256)
void softmax_rows(float* __restrict__ S, int n)
{
    __shared__ float red[256];
    const int tid = threadIdx.x;
    float* row = S + (size_t)blockIdx.x * n;

    // 1) row max
    float m = -INFINITY;
    for (int i = tid; i < n; i += 256) m = fmaxf(m, row[i]);
    red[tid] = m;
    __syncthreads();
    for (int s = 128; s > 0; s >>= 1) {
        if (tid < s) red[tid] = fmaxf(red[tid], red[tid + s]);
        __syncthreads();
    }
    m = red[0];
    __syncthreads();

    // 2) exp + sum
    float sum = 0.0f;
    for (int i = tid; i < n; i += 256) {
        const float e = expf(row[i] - m);
        row[i] = e;
        sum += e;
    }
    red[tid] = sum;
    __syncthreads();
    for (int s = 128; s > 0; s >>= 1) {
        if (tid < s) red[tid] += red[tid + s];
        __syncthreads();
    }
    const float inv = 1.0f / red[0];
    __syncthreads();

    // 3) normalize
    for (int i = tid; i < n; i += 256) row[i] *= inv;
}

// ---------------------------------------------------------------------------
extern "C" void kernel_launch(void* const* d_in, const int* in_sizes, int n_in,
                              void* d_out, int out_size)
{
    const float* X  = (const float*)d_in[0];
    const float* Wq = (const float*)d_in[1];
    const float* Wk = (const float*)d_in[2];
    const float* Wv = (const float*)d_in[3];
    float* out = (float*)d_out;

    float *Q, *K, *V, *S;
    cudaGetSymbolAddress((void**)&Q, g_Q);
    cudaGetSymbolAddress((void**)&K, g_K);
    cudaGetSymbolAddress((void**)&V, g_V);
    cudaGetSymbolAddress((void**)&S, g_S);

    const dim3 blk(256);
    const dim3 grid_qkv(DIM / 128, SEQ / 128);   // (8, 32)
    const dim3 grid_ss (SEQ / 128, SEQ / 128);   // (32, 32)
    const dim3 grid_out(DIM / 128, SEQ / 128);   // (8, 32)

    // Q, K, V projections (NN)
    sgemm128<0><<<grid_qkv, blk>>>(X, Wq, Q, SEQ, DIM, DIM, 1.0f);
    sgemm128<0><<<grid_qkv, blk>>>(X, Wk, K, SEQ, DIM, DIM, 1.0f);
    sgemm128<0><<<grid_qkv, blk>>>(X, Wv, V, SEQ, DIM, DIM, 1.0f);

    // S = (Q @ K^T) * 1/sqrt(1024)   (NT)
    sgemm128<1><<<grid_ss, blk>>>(Q, K, S, SEQ, SEQ, DIM, 0.03125f);

    // softmax rows of S, in place
    softmax_rows<<<SEQ, blk>>>(S, SEQ);

    // out = S @ V   (NN)
    sgemm128<0><<<grid_out, blk>>>(S, V, out, SEQ, DIM, SEQ, 1.0f);
}